// round 15
// baseline (speedup 1.0000x reference)
#include <cuda_runtime.h>
#include <cuda_fp16.h>
#include <cstdint>
#include <math.h>

// ---------------------------------------------------------------------------
// Problem constants
// ---------------------------------------------------------------------------
#define BATCH 4
#define SEQ   4096
#define DIM   512
#define ROWS  (BATCH * SEQ)          // 16384
#define EPS_THR 0.1f
#define BAND    4e-4f
#define LN_EPS  1e-5f
#define NORM_EPS 1e-12f
#define LO_SCALE 2048.0f             // 2^11
#define LO_INV   (1.0f / 2048.0f)

// ---------------------------------------------------------------------------
// Scratch (__device__ globals; no runtime allocation)
// ---------------------------------------------------------------------------
__device__ float g_q   [(size_t)ROWS * DIM];          // fp32 q / qn
__device__ half  g_qn16[(size_t)ROWS * DIM];          // qn fp16
__device__ half  g_x16 [(size_t)ROWS * DIM];          // x fp16 hi
__device__ half  g_xlo [(size_t)ROWS * DIM];          // x fp16 lo * 2^11
__device__ half  g_w16 [(size_t)DIM * DIM];           // W_v fp16
__device__ half  g_whi [(size_t)DIM * DIM];           // W_qk fp16 hi
__device__ half  g_wlo [(size_t)DIM * DIM];           // W_qk fp16 lo * 2^11
__device__ half  g_v16 [(size_t)ROWS * DIM];          // v fp16 row-major
__device__ half  g_s16 [(size_t)BATCH * SEQ * SEQ];   // masked attn fp16

// ---------------------------------------------------------------------------
// PTX helpers (arch-agnostic: sm_80+)
// ---------------------------------------------------------------------------
__device__ __forceinline__ uint32_t smem_u32(const void* p) {
    uint32_t a;
    asm("{ .reg .u64 t; cvta.to.shared.u64 t, %1; cvt.u32.u64 %0, t; }"
        : "=r"(a) : "l"(p));
    return a;
}

__device__ __forceinline__ void cp16(uint32_t dst, const void* src) {
    asm volatile("cp.async.cg.shared.global [%0], [%1], 16;" :: "r"(dst), "l"(src));
}
#define CP_COMMIT() asm volatile("cp.async.commit_group;" ::: "memory")
#define CP_WAIT(n)  asm volatile("cp.async.wait_group %0;" :: "n"(n) : "memory")

#define LDSM4(r0, r1, r2, r3, addr) \
    asm volatile("ldmatrix.sync.aligned.m8n8.x4.shared.b16 {%0,%1,%2,%3},[%4];" \
                 : "=r"(r0), "=r"(r1), "=r"(r2), "=r"(r3) : "r"(addr))

__device__ __forceinline__ void mma_fp(float* c, const uint32_t* a, const uint32_t* b) {
    asm volatile(
        "mma.sync.aligned.m16n8k16.row.col.f32.f16.f16.f32 "
        "{%0,%1,%2,%3},{%4,%5,%6,%7},{%8,%9},{%0,%1,%2,%3};"
        : "+f"(c[0]), "+f"(c[1]), "+f"(c[2]), "+f"(c[3])
        : "r"(a[0]), "r"(a[1]), "r"(a[2]), "r"(a[3]), "r"(b[0]), "r"(b[1]));
}

#define SWZC(c, r) ((uint32_t)(c) ^ ((((uint32_t)(r)) & 7u) << 4))

#define KC      64
#define PART_B  16384                  // 128 rows x 128 bytes
#define TSTRIDE 136

// ---------------------------------------------------------------------------
// Split kernels: fp32 -> fp16 hi + scaled lo
// ---------------------------------------------------------------------------
__global__ __launch_bounds__(256) void split_x_kernel(
    const float* __restrict__ src, half* __restrict__ dhi, half* __restrict__ dlo, long n)
{
    long i = ((long)blockIdx.x * 256 + threadIdx.x) * 4;
    if (i < n) {
        float4 f = *reinterpret_cast<const float4*>(src + i);
        float fv[4] = { f.x, f.y, f.z, f.w };
        half hi[4], lo[4];
#pragma unroll
        for (int k = 0; k < 4; k++) {
            hi[k] = __float2half_rn(fv[k]);
            lo[k] = __float2half_rn((fv[k] - __half2float(hi[k])) * LO_SCALE);
        }
        *reinterpret_cast<uint2*>(dhi + i) = *reinterpret_cast<uint2*>(hi);
        *reinterpret_cast<uint2*>(dlo + i) = *reinterpret_cast<uint2*>(lo);
    }
}

__global__ __launch_bounds__(256) void split_w_kernel(
    const float* __restrict__ wqk, const float* __restrict__ wv,
    half* __restrict__ whi, half* __restrict__ wlo, half* __restrict__ w16)
{
    long i = ((long)blockIdx.x * 256 + threadIdx.x) * 4;
    if (i < (long)DIM * DIM) {
        float4 f = *reinterpret_cast<const float4*>(wqk + i);
        float fv[4] = { f.x, f.y, f.z, f.w };
        half hi[4], lo[4];
#pragma unroll
        for (int k = 0; k < 4; k++) {
            hi[k] = __float2half_rn(fv[k]);
            lo[k] = __float2half_rn((fv[k] - __half2float(hi[k])) * LO_SCALE);
        }
        *reinterpret_cast<uint2*>(whi + i) = *reinterpret_cast<uint2*>(hi);
        *reinterpret_cast<uint2*>(wlo + i) = *reinterpret_cast<uint2*>(lo);

        float4 g = *reinterpret_cast<const float4*>(wv + i);
        half2 h0 = __floats2half2_rn(g.x, g.y);
        half2 h1 = __floats2half2_rn(g.z, g.w);
        uint2 u;
        u.x = *reinterpret_cast<uint32_t*>(&h0);
        u.y = *reinterpret_cast<uint32_t*>(&h1);
        *reinterpret_cast<uint2*>(w16 + i) = u;
    }
}

// ---------------------------------------------------------------------------
// Block reduce (128 threads)
// ---------------------------------------------------------------------------
__device__ __forceinline__ float block_reduce_sum_128(float v)
{
    __shared__ float sh[4];
#pragma unroll
    for (int o = 16; o > 0; o >>= 1) v += __shfl_down_sync(0xffffffffu, v, o);
    int lane = threadIdx.x & 31, w = threadIdx.x >> 5;
    if (lane == 0) sh[w] = v;
    __syncthreads();
    float total = sh[0] + sh[1] + sh[2] + sh[3];
    __syncthreads();
    return total;
}

__global__ __launch_bounds__(128) void l2norm_kernel(
    float* __restrict__ q, half* __restrict__ q16)
{
    long base = (long)blockIdx.x * DIM;
    float* p = q + base;
    float s = 0.0f;
#pragma unroll
    for (int i = threadIdx.x; i < DIM; i += 128) { float v = p[i]; s += v * v; }
    float total = block_reduce_sum_128(s);
    float inv = 1.0f / fmaxf(sqrtf(total), NORM_EPS);
#pragma unroll
    for (int i = threadIdx.x; i < DIM; i += 128) {
        float v = p[i] * inv;
        p[i] = v;
        q16[base + i] = __float2half_rn(v);
    }
}

// ---------------------------------------------------------------------------
// q projection: 3-pass fp16-split mma. Single-buffered 64KB stage, pass-split
// ks loops (16 live frag regs), __launch_bounds__(512,2) -> 2 CTAs/SM.
// Cross-CTA co-residency hides load latency.
// ---------------------------------------------------------------------------
#define Q_STAGE (4 * PART_B)          // 64KB single stage

__global__ __launch_bounds__(512, 2) void q_mma_kernel(
    const half* __restrict__ Ahi, const half* __restrict__ Alo,
    const half* __restrict__ Bhi, const half* __restrict__ Blo,
    float* __restrict__ C)
{
    extern __shared__ __align__(1024) char sm[];

    int tid = threadIdx.x;
    int wid = tid >> 5, lane = tid & 31;
    int wm = wid & 3, wn = wid >> 2;
    int bx = blockIdx.x, by = blockIdx.y;

    const half* Ah = Ahi + (long)by * 128 * DIM;
    const half* Al = Alo + (long)by * 128 * DIM;
    const half* Bh = Bhi + (long)bx * 128 * DIM;
    const half* Bl = Blo + (long)bx * 128 * DIM;

    uint32_t smb = smem_u32(sm);
    const int NC = DIM / KC;   // 8

    float acc0[2][4][4], acc1[2][4][4];
#pragma unroll
    for (int mt = 0; mt < 2; mt++)
#pragma unroll
        for (int nt = 0; nt < 4; nt++)
#pragma unroll
            for (int i = 0; i < 4; i++) { acc0[mt][nt][i] = 0.0f; acc1[mt][nt][i] = 0.0f; }

    uint32_t pAh = smb, pAl = smb + PART_B, pBh = smb + 2 * PART_B, pBl = smb + 3 * PART_B;

    for (int c = 0; c < NC; c++) {
        int k0 = c * KC;
        const half* srcs[4] = { Ah, Al, Bh, Bl };
#pragma unroll
        for (int p = 0; p < 4; p++) {
#pragma unroll
            for (int i = 0; i < 2; i++) {
                int idx = tid + i * 512;
                int r = idx >> 3, c8 = idx & 7;
                uint32_t dst = smb + (uint32_t)p * PART_B + (uint32_t)r * 128 + SWZC(c8 * 16, r);
                cp16(dst, srcs[p] + (long)r * DIM + k0 + c8 * 8);
            }
        }
        CP_COMMIT();
        CP_WAIT(0);
        __syncthreads();

        // pass 1: hi*hi -> acc0
#pragma unroll
        for (int ks = 0; ks < 4; ks++) {
            uint32_t af[2][4], bf2[2][4];
#pragma unroll
            for (int mt = 0; mt < 2; mt++) {
                int arow = wm * 32 + mt * 16 + (lane & 15);
                uint32_t off = (uint32_t)arow * 128 + SWZC(ks * 32 + (lane >> 4) * 16, arow);
                LDSM4(af[mt][0], af[mt][1], af[mt][2], af[mt][3], pAh + off);
            }
#pragma unroll
            for (int np = 0; np < 2; np++) {
                int brow = wn * 32 + np * 16 + (lane & 7) + ((lane >> 4) << 3);
                uint32_t off = (uint32_t)brow * 128 +
                               SWZC(ks * 32 + ((lane >> 3) & 1) * 16, brow);
                LDSM4(bf2[np][0], bf2[np][1], bf2[np][2], bf2[np][3], pBh + off);
            }
#pragma unroll
            for (int np = 0; np < 2; np++)
#pragma unroll
                for (int mt = 0; mt < 2; mt++) {
                    mma_fp(acc0[mt][np * 2 + 0], af[mt], bf2[np] + 0);
                    mma_fp(acc0[mt][np * 2 + 1], af[mt], bf2[np] + 2);
                }
        }
        // pass 2: hi*lo -> acc1
#pragma unroll
        for (int ks = 0; ks < 4; ks++) {
            uint32_t af[2][4], bf2[2][4];
#pragma unroll
            for (int mt = 0; mt < 2; mt++) {
                int arow = wm * 32 + mt * 16 + (lane & 15);
                uint32_t off = (uint32_t)arow * 128 + SWZC(ks * 32 + (lane >> 4) * 16, arow);
                LDSM4(af[mt][0], af[mt][1], af[mt][2], af[mt][3], pAh + off);
            }
#pragma unroll
            for (int np = 0; np < 2; np++) {
                int brow = wn * 32 + np * 16 + (lane & 7) + ((lane >> 4) << 3);
                uint32_t off = (uint32_t)brow * 128 +
                               SWZC(ks * 32 + ((lane >> 3) & 1) * 16, brow);
                LDSM4(bf2[np][0], bf2[np][1], bf2[np][2], bf2[np][3], pBl + off);
            }
#pragma unroll
            for (int np = 0; np < 2; np++)
#pragma unroll
                for (int mt = 0; mt < 2; mt++) {
                    mma_fp(acc1[mt][np * 2 + 0], af[mt], bf2[np] + 0);
                    mma_fp(acc1[mt][np * 2 + 1], af[mt], bf2[np] + 2);
                }
        }
        // pass 3: lo*hi -> acc1
#pragma unroll
        for (int ks = 0; ks < 4; ks++) {
            uint32_t af[2][4], bf2[2][4];
#pragma unroll
            for (int mt = 0; mt < 2; mt++) {
                int arow = wm * 32 + mt * 16 + (lane & 15);
                uint32_t off = (uint32_t)arow * 128 + SWZC(ks * 32 + (lane >> 4) * 16, arow);
                LDSM4(af[mt][0], af[mt][1], af[mt][2], af[mt][3], pAl + off);
            }
#pragma unroll
            for (int np = 0; np < 2; np++) {
                int brow = wn * 32 + np * 16 + (lane & 7) + ((lane >> 4) << 3);
                uint32_t off = (uint32_t)brow * 128 +
                               SWZC(ks * 32 + ((lane >> 3) & 1) * 16, brow);
                LDSM4(bf2[np][0], bf2[np][1], bf2[np][2], bf2[np][3], pBh + off);
            }
#pragma unroll
            for (int np = 0; np < 2; np++)
#pragma unroll
                for (int mt = 0; mt < 2; mt++) {
                    mma_fp(acc1[mt][np * 2 + 0], af[mt], bf2[np] + 0);
                    mma_fp(acc1[mt][np * 2 + 1], af[mt], bf2[np] + 2);
                }
        }
        __syncthreads();
    }

#pragma unroll
    for (int mt = 0; mt < 2; mt++) {
#pragma unroll
        for (int hf = 0; hf < 2; hf++) {
            int gr = by * 128 + wm * 32 + mt * 16 + (lane >> 2) + hf * 8;
#pragma unroll
            for (int nt = 0; nt < 4; nt++) {
                int gn0 = bx * 128 + wn * 32 + nt * 8 + (lane & 3) * 2;
                float2 f2;
                f2.x = acc0[mt][nt][hf * 2 + 0] + acc1[mt][nt][hf * 2 + 0] * LO_INV;
                f2.y = acc0[mt][nt][hf * 2 + 1] + acc1[mt][nt][hf * 2 + 1] * LO_INV;
                *reinterpret_cast<float2*>(C + (long)gr * DIM + gn0) = f2;
            }
        }
    }
}

// ---------------------------------------------------------------------------
// S kernel: 1-pass fp16 mma; triangular + mirror; cooperative rescue. (512,2)
// ---------------------------------------------------------------------------
#define S1_STAGE (2 * PART_B)
#define S1_SMEM  (2 * S1_STAGE)
#define RMAX 512

__global__ __launch_bounds__(512, 2) void s_mma_kernel(
    const half* __restrict__ qn16, const float* __restrict__ qn,
    half* __restrict__ S)
{
    extern __shared__ __align__(1024) char sm[];
    __shared__ int rcount;
    __shared__ unsigned short rlist[RMAX];

    int tid = threadIdx.x;
    int wid = tid >> 5, lane = tid & 31;
    int wm = wid & 3, wn = wid >> 2;
    int bz = blockIdx.z;

    int t = blockIdx.x;
    int bi = (int)((sqrtf(8.0f * (float)t + 1.0f) - 1.0f) * 0.5f);
    while ((bi + 1) * (bi + 2) / 2 <= t) ++bi;
    while (bi * (bi + 1) / 2 > t) --bi;
    int by = t - bi * (bi + 1) / 2;
    int bx = bi;

    const half* At = qn16 + (long)bz * SEQ * DIM + (long)by * 128 * DIM;
    const half* Bt = qn16 + (long)bz * SEQ * DIM + (long)bx * 128 * DIM;

    uint32_t smb = smem_u32(sm);
    const int NC = DIM / KC;

    auto issue_chunk = [&](int c) {
        uint32_t st = smb + (uint32_t)(c & 1) * S1_STAGE;
        int k0 = c * KC;
        const half* srcs[2] = { At, Bt };
#pragma unroll
        for (int p = 0; p < 2; p++) {
#pragma unroll
            for (int i = 0; i < 2; i++) {
                int idx = tid + i * 512;
                int r = idx >> 3, c8 = idx & 7;
                uint32_t dst = st + (uint32_t)p * PART_B + (uint32_t)r * 128 + SWZC(c8 * 16, r);
                cp16(dst, srcs[p] + (long)r * DIM + k0 + c8 * 8);
            }
        }
        CP_COMMIT();
    };

    if (tid == 0) rcount = 0;

    float acc[2][4][4];
#pragma unroll
    for (int mt = 0; mt < 2; mt++)
#pragma unroll
        for (int nt = 0; nt < 4; nt++)
#pragma unroll
            for (int i = 0; i < 4; i++) acc[mt][nt][i] = 0.0f;

    issue_chunk(0);

    for (int c = 0; c < NC; c++) {
        if (c + 1 < NC) { issue_chunk(c + 1); CP_WAIT(1); }
        else            { CP_WAIT(0); }
        __syncthreads();

        uint32_t base = smb + (uint32_t)(c & 1) * S1_STAGE;
        uint32_t pA = base, pB = base + PART_B;

#pragma unroll
        for (int ks = 0; ks < 4; ks++) {
            uint32_t af[2][4], bfr[2][4];
#pragma unroll
            for (int mt = 0; mt < 2; mt++) {
                int arow = wm * 32 + mt * 16 + (lane & 15);
                uint32_t off = (uint32_t)arow * 128 + SWZC(ks * 32 + (lane >> 4) * 16, arow);
                LDSM4(af[mt][0], af[mt][1], af[mt][2], af[mt][3], pA + off);
            }
#pragma unroll
            for (int np = 0; np < 2; np++) {
                int brow = wn * 32 + np * 16 + (lane & 7) + ((lane >> 4) << 3);
                uint32_t off = (uint32_t)brow * 128 +
                               SWZC(ks * 32 + ((lane >> 3) & 1) * 16, brow);
                LDSM4(bfr[np][0], bfr[np][1], bfr[np][2], bfr[np][3], pB + off);
            }
#pragma unroll
            for (int np = 0; np < 2; np++)
#pragma unroll
                for (int mt = 0; mt < 2; mt++) {
                    mma_fp(acc[mt][np * 2 + 0], af[mt], bfr[np] + 0);
                    mma_fp(acc[mt][np * 2 + 1], af[mt], bfr[np] + 2);
                }
        }
        __syncthreads();
    }

    // ---- epilogue: store provisional + collect band entries ----
    const float* qnB = qn + (long)bz * SEQ * DIM;
    half* smT = reinterpret_cast<half*>(sm);
    half* Sb = S + (long)bz * SEQ * SEQ;
    bool mirror = (bx != by);

#pragma unroll
    for (int mt = 0; mt < 2; mt++) {
#pragma unroll
        for (int hf = 0; hf < 2; hf++) {
            int lr = wm * 32 + mt * 16 + (lane >> 2) + hf * 8;
            int gr = by * 128 + lr;
#pragma unroll
            for (int nt = 0; nt < 4; nt++) {
                float s0 = acc[mt][nt][hf * 2 + 0];
                float s1 = acc[mt][nt][hf * 2 + 1];
                int ln0 = wn * 32 + nt * 8 + (lane & 3) * 2;
                int gn0 = bx * 128 + ln0;
                if (fabsf(s0 - EPS_THR) < BAND) {
                    int p = atomicAdd(&rcount, 1);
                    if (p < RMAX) rlist[p] = (unsigned short)((lr << 8) | ln0);
                    else {
                        const float* qA = qnB + (long)gr * DIM;
                        const float* qB = qnB + (long)gn0 * DIM;
                        float a2 = 0.f;
#pragma unroll 8
                        for (int k = 0; k < DIM; k++) a2 = fmaf(qA[k], qB[k], a2);
                        s0 = a2;
                    }
                }
                if (fabsf(s1 - EPS_THR) < BAND) {
                    int p = atomicAdd(&rcount, 1);
                    if (p < RMAX) rlist[p] = (unsigned short)((lr << 8) | (ln0 + 1));
                    else {
                        const float* qA = qnB + (long)gr * DIM;
                        const float* qB = qnB + (long)(gn0 + 1) * DIM;
                        float a2 = 0.f;
#pragma unroll 8
                        for (int k = 0; k < DIM; k++) a2 = fmaf(qA[k], qB[k], a2);
                        s1 = a2;
                    }
                }
                s0 = (s0 > EPS_THR) ? s0 : 0.f;
                s1 = (s1 > EPS_THR) ? s1 : 0.f;
                half2 hh = __floats2half2_rn(s0, s1);
                *reinterpret_cast<half2*>(Sb + (long)gr * SEQ + gn0) = hh;
                if (mirror) {
                    smT[ln0 * TSTRIDE + lr]       = hh.x;
                    smT[(ln0 + 1) * TSTRIDE + lr] = hh.y;
                }
            }
        }
    }
    __syncthreads();

    // ---- warp-cooperative rescue fix-up ----
    {
        int nr = rcount < RMAX ? rcount : RMAX;
        for (int i = wid; i < nr; i += 16) {
            int code = rlist[i];
            int lr = code >> 8, ln = code & 255;
            int gr = by * 128 + lr, gn = bx * 128 + ln;
            const float* qA = qnB + (long)gr * DIM;
            const float* qB = qnB + (long)gn * DIM;
            float part = 0.f;
            int k0 = lane * 16;
#pragma unroll
            for (int k = 0; k < 16; k++) part = fmaf(qA[k0 + k], qB[k0 + k], part);
#pragma unroll
            for (int o = 16; o > 0; o >>= 1) part += __shfl_down_sync(0xffffffffu, part, o);
            if (lane == 0) {
                float sx = (part > EPS_THR) ? part : 0.f;
                half h = __float2half_rn(sx);
                Sb[(long)gr * SEQ + gn] = h;
                if (mirror) smT[ln * TSTRIDE + lr] = h;
            }
        }
    }

    if (mirror) {
        __syncthreads();
        int r2 = tid >> 2;
        int q4 = tid & 3;
#pragma unroll
        for (int g = 0; g < 4; g++) {
            int j = q4 + g * 4;
            uint4 v = *reinterpret_cast<const uint4*>(smT + r2 * TSTRIDE + j * 8);
            *reinterpret_cast<uint4*>(Sb + (long)(bx * 128 + r2) * SEQ + by * 128 + j * 8) = v;
        }
    }
}

// ---------------------------------------------------------------------------
// fp16 1-pass mma GEMM, fp16 store: v = x * W_v^T. (512,2)
// ---------------------------------------------------------------------------
#define H_STAGE (2 * PART_B)
#define H_SMEM  (2 * H_STAGE)

__global__ __launch_bounds__(512, 2) void h_mma_kernel(
    const half* __restrict__ A, long ldA,
    const half* __restrict__ B, long ldB,
    int K, half* __restrict__ Oh, long ldO)
{
    extern __shared__ __align__(1024) char sm[];

    int tid = threadIdx.x;
    int wid = tid >> 5, lane = tid & 31;
    int wm = wid & 3, wn = wid >> 2;
    int bx = blockIdx.x, by = blockIdx.y;

    const half* At = A + (long)by * 128 * ldA;
    const half* Bt = B + (long)bx * 128 * ldB;

    uint32_t smb = smem_u32(sm);
    int NC = K / KC;

    auto issue_chunk = [&](int c) {
        uint32_t st = smb + (uint32_t)(c & 1) * H_STAGE;
        int k0 = c * KC;
        const half* srcs[2] = { At, Bt };
        long lds[2] = { ldA, ldB };
#pragma unroll
        for (int p = 0; p < 2; p++) {
#pragma unroll
            for (int i = 0; i < 2; i++) {
                int idx = tid + i * 512;
                int r = idx >> 3, c8 = idx & 7;
                uint32_t dst = st + (uint32_t)p * PART_B + (uint32_t)r * 128 + SWZC(c8 * 16, r);
                cp16(dst, srcs[p] + (long)r * lds[p] + k0 + c8 * 8);
            }
        }
        CP_COMMIT();
    };

    float acc[2][4][4];
#pragma unroll
    for (int mt = 0; mt < 2; mt++)
#pragma unroll
        for (int nt = 0; nt < 4; nt++)
#pragma unroll
            for (int i = 0; i < 4; i++) acc[mt][nt][i] = 0.0f;

    issue_chunk(0);

    for (int c = 0; c < NC; c++) {
        if (c + 1 < NC) { issue_chunk(c + 1); CP_WAIT(1); }
        else            { CP_WAIT(0); }
        __syncthreads();

        uint32_t base = smb + (uint32_t)(c & 1) * H_STAGE;
        uint32_t pA = base, pB = base + PART_B;

#pragma unroll
        for (int ks = 0; ks < 4; ks++) {
            uint32_t af[2][4], bfr[2][4];
#pragma unroll
            for (int mt = 0; mt < 2; mt++) {
                int arow = wm * 32 + mt * 16 + (lane & 15);
                uint32_t off = (uint32_t)arow * 128 + SWZC(ks * 32 + (lane >> 4) * 16, arow);
                LDSM4(af[mt][0], af[mt][1], af[mt][2], af[mt][3], pA + off);
            }
#pragma unroll
            for (int np = 0; np < 2; np++) {
                int brow = wn * 32 + np * 16 + (lane & 7) + ((lane >> 4) << 3);
                uint32_t off = (uint32_t)brow * 128 +
                               SWZC(ks * 32 + ((lane >> 3) & 1) * 16, brow);
                LDSM4(bfr[np][0], bfr[np][1], bfr[np][2], bfr[np][3], pB + off);
            }
#pragma unroll
            for (int np = 0; np < 2; np++)
#pragma unroll
                for (int mt = 0; mt < 2; mt++) {
                    mma_fp(acc[mt][np * 2 + 0], af[mt], bfr[np] + 0);
                    mma_fp(acc[mt][np * 2 + 1], af[mt], bfr[np] + 2);
                }
        }
        __syncthreads();
    }

#pragma unroll
    for (int mt = 0; mt < 2; mt++) {
#pragma unroll
        for (int hf = 0; hf < 2; hf++) {
            int gr = by * 128 + wm * 32 + mt * 16 + (lane >> 2) + hf * 8;
#pragma unroll
            for (int nt = 0; nt < 4; nt++) {
                int gn0 = bx * 128 + wn * 32 + nt * 8 + (lane & 3) * 2;
                half2 h = __floats2half2_rn(acc[mt][nt][hf * 2 + 0],
                                            acc[mt][nt][hf * 2 + 1]);
                *reinterpret_cast<half2*>(Oh + (long)gr * ldO + gn0) = h;
            }
        }
    }
}

// ---------------------------------------------------------------------------
// Sparse A*V + fused LayerNorm (R10/R13 4-phase version — frozen).
// ---------------------------------------------------------------------------
__global__ __launch_bounds__(128) void av_ln_kernel(
    const half* __restrict__ S, const half* __restrict__ V,
    const float* __restrict__ gamma, const float* __restrict__ beta,
    float* __restrict__ out)
{
    int gr = blockIdx.x;
    int bz = gr >> 12;
    int n  = gr & (SEQ - 1);
    const half* Srow = S + ((long)bz * SEQ + n) * SEQ;
    const half* Vb   = V + (long)bz * SEQ * DIM;
    int tid = threadIdx.x, lane = tid & 31, wrp = tid >> 5;

    __shared__ int   s_idx[1024];
    __shared__ float s_val[1024];
    __shared__ int   s_wbase[4];

    float a0 = 0.f, a1 = 0.f, a2 = 0.f, a3 = 0.f;

#pragma unroll 1
    for (int ch = 0; ch < SEQ / 1024; ch++) {
        uint4 w = *reinterpret_cast<const uint4*>(Srow + ch * 1024 + tid * 8);
        uint32_t ws[4] = { w.x, w.y, w.z, w.w };
        uint16_t hs[8];
#pragma unroll
        for (int k = 0; k < 4; k++) {
            hs[2 * k]     = (uint16_t)(ws[k] & 0xFFFFu);
            hs[2 * k + 1] = (uint16_t)(ws[k] >> 16);
        }
        int nz = 0;
#pragma unroll
        for (int k = 0; k < 8; k++) nz += (hs[k] != 0);

        int inc = nz;
#pragma unroll
        for (int o = 1; o < 32; o <<= 1) {
            int vsh = __shfl_up_sync(0xffffffffu, inc, o);
            if (lane >= o) inc += vsh;
        }
        if (lane == 31) s_wbase[wrp] = inc;
        __syncthreads();
        int wb = 0;
#pragma unroll
        for (int ww = 0; ww < 4; ww++) if (ww < wrp) wb += s_wbase[ww];
        int total = s_wbase[0] + s_wbase[1] + s_wbase[2] + s_wbase[3];
        int pos = wb + inc - nz;
#pragma unroll
        for (int k = 0; k < 8; k++) {
            if (hs[k] != 0) {
                __half_raw hr; hr.x = hs[k];
                s_idx[pos] = ch * 1024 + tid * 8 + k;
                s_val[pos] = __half2float((half)hr);
                pos++;
            }
        }
        __syncthreads();

        int i = 0;
        for (; i + 4 <= total; i += 4) {
            float sv0 = s_val[i],     sv1 = s_val[i + 1];
            float sv2 = s_val[i + 2], sv3 = s_val[i + 3];
            int m0 = s_idx[i],     m1 = s_idx[i + 1];
            int m2 = s_idx[i + 2], m3 = s_idx[i + 3];
            uint2 v0 = *reinterpret_cast<const uint2*>(Vb + (long)m0 * DIM + tid * 4);
            uint2 v1 = *reinterpret_cast<const uint2*>(Vb + (long)m1 * DIM + tid * 4);
            uint2 v2 = *reinterpret_cast<const uint2*>(Vb + (long)m2 * DIM + tid * 4);
            uint2 v3 = *reinterpret_cast<const uint2*>(Vb + (long)m3 * DIM + tid * 4);
#define ACC4(vv, sv) do {                                           \
                half2 _h0 = *reinterpret_cast<half2*>(&(vv).x);     \
                half2 _h1 = *reinterpret_cast<half2*>(&(vv).y);     \
                float2 _f0 = __half22float2(_h0);                   \
                float2 _f1 = __half22float2(_h1);                   \
                a0 = fmaf((sv), _f0.x, a0);                         \
                a1 = fmaf((sv), _f0.y, a1);                         \
                a2 = fmaf((sv), _f1.x, a2);                         \
                a3 = fmaf((sv), _f1.y, a3);                         \
            } while (0)
            ACC4(v0, sv0); ACC4(v1, sv1); ACC4(v2, sv2); ACC4(v3, sv3);
        }
        for (; i < total; i++) {
            float sv = s_val[i];
            int m = s_idx[i];
            uint2 vv = *reinterpret_cast<const uint2*>(Vb + (long)m * DIM + tid * 4);
            ACC4(vv, sv);
        }
#undef ACC4
        __syncthreads();
    }

    float s1 = a0 + a1 + a2 + a3;
    float s2 = a0 * a0 + a1 * a1 + a2 * a2 + a3 * a3;
    float ts1 = block_reduce_sum_128(s1);
    float ts2 = block_reduce_sum_128(s2);
    float mean = ts1 * (1.0f / DIM);
    float var  = ts2 * (1.0f / DIM) - mean * mean;
    float inv = rsqrtf(var + LN_EPS);

    float4 g = *reinterpret_cast<const float4*>(gamma + tid * 4);
    float4 b = *reinterpret_cast<const float4*>(beta + tid * 4);
    float4 o;
    o.x = (a0 - mean) * inv * g.x + b.x;
    o.y = (a1 - mean) * inv * g.y + b.y;
    o.z = (a2 - mean) * inv * g.z + b.z;
    o.w = (a3 - mean) * inv * g.w + b.w;
    *reinterpret_cast<float4*>(out + (long)gr * DIM + tid * 4) = o;
}

// ---------------------------------------------------------------------------
// Launch
// ---------------------------------------------------------------------------
extern "C" void kernel_launch(void* const* d_in, const int* in_sizes, int n_in,
                              void* d_out, int out_size)
{
    const float* x     = (const float*)d_in[0];
    const float* W_qk  = (const float*)d_in[1];
    const float* W_v   = (const float*)d_in[2];
    const float* gamma = (const float*)d_in[3];
    const float* beta  = (const float*)d_in[4];
    float* out = (float*)d_out;

    float* qp;
    half *qn16, *x16, *xlo, *w16, *whi, *wlo, *v16, *s16;
    cudaGetSymbolAddress((void**)&qp,   g_q);
    cudaGetSymbolAddress((void**)&qn16, g_qn16);
    cudaGetSymbolAddress((void**)&x16,  g_x16);
    cudaGetSymbolAddress((void**)&xlo,  g_xlo);
    cudaGetSymbolAddress((void**)&w16,  g_w16);
    cudaGetSymbolAddress((void**)&whi,  g_whi);
    cudaGetSymbolAddress((void**)&wlo,  g_wlo);
    cudaGetSymbolAddress((void**)&v16,  g_v16);
    cudaGetSymbolAddress((void**)&s16,  g_s16);

    cudaFuncSetAttribute((const void*)q_mma_kernel, cudaFuncAttributeMaxDynamicSharedMemorySize, Q_STAGE);
    cudaFuncSetAttribute((const void*)s_mma_kernel, cudaFuncAttributeMaxDynamicSharedMemorySize, S1_SMEM);
    cudaFuncSetAttribute((const void*)h_mma_kernel, cudaFuncAttributeMaxDynamicSharedMemorySize, H_SMEM);

    // 1) splits
    split_x_kernel<<<((long)ROWS * DIM / 4 + 255) / 256, 256>>>(x, x16, xlo, (long)ROWS * DIM);
    split_w_kernel<<<((long)DIM * DIM / 4 + 255) / 256, 256>>>(W_qk, W_v, whi, wlo, w16);

    // 2) q = x * Wqk^T — 3-pass fp16 split, single-buffer, 2 CTAs/SM
    {
        dim3 grid(DIM / 128, ROWS / 128, 1);
        q_mma_kernel<<<grid, 512, Q_STAGE>>>(x16, xlo, whi, wlo, qp);
    }

    // 3) v = x * W_v^T (fp16 1-pass; row-major)
    {
        dim3 grid(DIM / 128, ROWS / 128, 1);
        h_mma_kernel<<<grid, 512, H_SMEM>>>(x16, DIM, w16, DIM, DIM, v16, DIM);
    }

    // 4) L2-normalize q rows + fp16 plane
    l2norm_kernel<<<ROWS, 128>>>(qp, qn16);

    // 5) S = Qn*Qn^T — 1-pass fp16, triangular + mirror, cooperative rescue
    {
        int nt = SEQ / 128;
        dim3 grid(nt * (nt + 1) / 2, 1, BATCH);
        s_mma_kernel<<<grid, 512, S1_SMEM>>>(qn16, qp, s16);
    }

    // 6) out = LayerNorm(S * V) — sparse gather, fused LN
    av_ln_kernel<<<ROWS, 128>>>(s16, v16, gamma, beta, out);
}

// round 16
// speedup vs baseline: 1.5840x; 1.5840x over previous
#include <cuda_runtime.h>
#include <cuda_fp16.h>
#include <cstdint>
#include <math.h>

// ---------------------------------------------------------------------------
// Problem constants
// ---------------------------------------------------------------------------
#define BATCH 4
#define SEQ   4096
#define DIM   512
#define ROWS  (BATCH * SEQ)          // 16384
#define EPS_THR 0.1f
#define BAND    4e-4f
#define LN_EPS  1e-5f
#define NORM_EPS 1e-12f
#define LO_SCALE 2048.0f             // 2^11
#define LO_INV   (1.0f / 2048.0f)

// ---------------------------------------------------------------------------
// Scratch (__device__ globals; no runtime allocation)
// ---------------------------------------------------------------------------
__device__ float g_q   [(size_t)ROWS * DIM];          // fp32 q / qn
__device__ half  g_qn16[(size_t)ROWS * DIM];          // qn fp16
__device__ half  g_x16 [(size_t)ROWS * DIM];          // x fp16 hi
__device__ half  g_xlo [(size_t)ROWS * DIM];          // x fp16 lo * 2^11
__device__ half  g_w16 [(size_t)DIM * DIM];           // W_v fp16
__device__ half  g_whi [(size_t)DIM * DIM];           // W_qk fp16 hi
__device__ half  g_wlo [(size_t)DIM * DIM];           // W_qk fp16 lo * 2^11
__device__ half  g_v16 [(size_t)ROWS * DIM];          // v fp16 row-major
__device__ half  g_s16 [(size_t)BATCH * SEQ * SEQ];   // masked attn fp16

// ---------------------------------------------------------------------------
// PTX helpers (arch-agnostic: sm_80+)
// ---------------------------------------------------------------------------
__device__ __forceinline__ uint32_t smem_u32(const void* p) {
    uint32_t a;
    asm("{ .reg .u64 t; cvta.to.shared.u64 t, %1; cvt.u32.u64 %0, t; }"
        : "=r"(a) : "l"(p));
    return a;
}

__device__ __forceinline__ void cp16(uint32_t dst, const void* src) {
    asm volatile("cp.async.cg.shared.global [%0], [%1], 16;" :: "r"(dst), "l"(src));
}
#define CP_COMMIT() asm volatile("cp.async.commit_group;" ::: "memory")
#define CP_WAIT(n)  asm volatile("cp.async.wait_group %0;" :: "n"(n) : "memory")

#define LDSM4(r0, r1, r2, r3, addr) \
    asm volatile("ldmatrix.sync.aligned.m8n8.x4.shared.b16 {%0,%1,%2,%3},[%4];" \
                 : "=r"(r0), "=r"(r1), "=r"(r2), "=r"(r3) : "r"(addr))

__device__ __forceinline__ void mma_fp(float* c, const uint32_t* a, const uint32_t* b) {
    asm volatile(
        "mma.sync.aligned.m16n8k16.row.col.f32.f16.f16.f32 "
        "{%0,%1,%2,%3},{%4,%5,%6,%7},{%8,%9},{%0,%1,%2,%3};"
        : "+f"(c[0]), "+f"(c[1]), "+f"(c[2]), "+f"(c[3])
        : "r"(a[0]), "r"(a[1]), "r"(a[2]), "r"(a[3]), "r"(b[0]), "r"(b[1]));
}

#define SWZC(c, r) ((uint32_t)(c) ^ ((((uint32_t)(r)) & 7u) << 4))

#define KC      64
#define PART_B  16384                  // 128 rows x 128 bytes
#define TSTRIDE 136                    // halves; 272B (16B-aligned) row stride

// ---------------------------------------------------------------------------
// Merged split kernel: x -> (x16, xlo); W_qk -> (whi, wlo); W_v -> w16
// ---------------------------------------------------------------------------
__global__ __launch_bounds__(256) void split_all_kernel(
    const float* __restrict__ x, half* __restrict__ x16, half* __restrict__ xlo,
    const float* __restrict__ wqk, const float* __restrict__ wv,
    half* __restrict__ whi, half* __restrict__ wlo, half* __restrict__ w16)
{
    long i = ((long)blockIdx.x * 256 + threadIdx.x) * 4;
    if (i < (long)ROWS * DIM) {
        float4 f = *reinterpret_cast<const float4*>(x + i);
        float fv[4] = { f.x, f.y, f.z, f.w };
        half hi[4], lo[4];
#pragma unroll
        for (int k = 0; k < 4; k++) {
            hi[k] = __float2half_rn(fv[k]);
            lo[k] = __float2half_rn((fv[k] - __half2float(hi[k])) * LO_SCALE);
        }
        *reinterpret_cast<uint2*>(x16 + i) = *reinterpret_cast<uint2*>(hi);
        *reinterpret_cast<uint2*>(xlo + i) = *reinterpret_cast<uint2*>(lo);
    }
    if (i < (long)DIM * DIM) {
        float4 f = *reinterpret_cast<const float4*>(wqk + i);
        float fv[4] = { f.x, f.y, f.z, f.w };
        half hi[4], lo[4];
#pragma unroll
        for (int k = 0; k < 4; k++) {
            hi[k] = __float2half_rn(fv[k]);
            lo[k] = __float2half_rn((fv[k] - __half2float(hi[k])) * LO_SCALE);
        }
        *reinterpret_cast<uint2*>(whi + i) = *reinterpret_cast<uint2*>(hi);
        *reinterpret_cast<uint2*>(wlo + i) = *reinterpret_cast<uint2*>(lo);

        float4 g = *reinterpret_cast<const float4*>(wv + i);
        half2 h0 = __floats2half2_rn(g.x, g.y);
        half2 h1 = __floats2half2_rn(g.z, g.w);
        uint2 u;
        u.x = *reinterpret_cast<uint32_t*>(&h0);
        u.y = *reinterpret_cast<uint32_t*>(&h1);
        *reinterpret_cast<uint2*>(w16 + i) = u;
    }
}

// ---------------------------------------------------------------------------
// Block reduce (128 threads)
// ---------------------------------------------------------------------------
__device__ __forceinline__ float block_reduce_sum_128(float v)
{
    __shared__ float sh[4];
#pragma unroll
    for (int o = 16; o > 0; o >>= 1) v += __shfl_down_sync(0xffffffffu, v, o);
    int lane = threadIdx.x & 31, w = threadIdx.x >> 5;
    if (lane == 0) sh[w] = v;
    __syncthreads();
    float total = sh[0] + sh[1] + sh[2] + sh[3];
    __syncthreads();
    return total;
}

__global__ __launch_bounds__(128) void l2norm_kernel(
    float* __restrict__ q, half* __restrict__ q16)
{
    long base = (long)blockIdx.x * DIM;
    float* p = q + base;
    float s = 0.0f;
#pragma unroll
    for (int i = threadIdx.x; i < DIM; i += 128) { float v = p[i]; s += v * v; }
    float total = block_reduce_sum_128(s);
    float inv = 1.0f / fmaxf(sqrtf(total), NORM_EPS);
#pragma unroll
    for (int i = threadIdx.x; i < DIM; i += 128) {
        float v = p[i] * inv;
        p[i] = v;
        q16[base + i] = __float2half_rn(v);
    }
}

// ---------------------------------------------------------------------------
// q projection: 3-pass fp16-split mma, double-buffered (R13 form, 1 CTA/SM).
// ---------------------------------------------------------------------------
#define Q_STAGE (4 * PART_B)
#define Q_SMEM  (2 * Q_STAGE)

__global__ __launch_bounds__(512, 1) void q_mma_kernel(
    const half* __restrict__ Ahi, const half* __restrict__ Alo,
    const half* __restrict__ Bhi, const half* __restrict__ Blo,
    float* __restrict__ C)
{
    extern __shared__ __align__(1024) char sm[];

    int tid = threadIdx.x;
    int wid = tid >> 5, lane = tid & 31;
    int wm = wid & 3, wn = wid >> 2;
    int bx = blockIdx.x, by = blockIdx.y;

    const half* Ah = Ahi + (long)by * 128 * DIM;
    const half* Al = Alo + (long)by * 128 * DIM;
    const half* Bh = Bhi + (long)bx * 128 * DIM;
    const half* Bl = Blo + (long)bx * 128 * DIM;

    uint32_t smb = smem_u32(sm);
    const int NC = DIM / KC;

    auto issue_chunk = [&](int c) {
        uint32_t st = smb + (uint32_t)(c & 1) * Q_STAGE;
        int k0 = c * KC;
        const half* srcs[4] = { Ah, Al, Bh, Bl };
#pragma unroll
        for (int p = 0; p < 4; p++) {
#pragma unroll
            for (int i = 0; i < 2; i++) {
                int idx = tid + i * 512;
                int r = idx >> 3, c8 = idx & 7;
                uint32_t dst = st + (uint32_t)p * PART_B + (uint32_t)r * 128 + SWZC(c8 * 16, r);
                cp16(dst, srcs[p] + (long)r * DIM + k0 + c8 * 8);
            }
        }
        CP_COMMIT();
    };

    float acc0[2][4][4], acc1[2][4][4];
#pragma unroll
    for (int mt = 0; mt < 2; mt++)
#pragma unroll
        for (int nt = 0; nt < 4; nt++)
#pragma unroll
            for (int i = 0; i < 4; i++) { acc0[mt][nt][i] = 0.0f; acc1[mt][nt][i] = 0.0f; }

    issue_chunk(0);

    for (int c = 0; c < NC; c++) {
        if (c + 1 < NC) { issue_chunk(c + 1); CP_WAIT(1); }
        else            { CP_WAIT(0); }
        __syncthreads();

        uint32_t base = smb + (uint32_t)(c & 1) * Q_STAGE;
        uint32_t pAh = base, pAl = base + PART_B, pBh = base + 2 * PART_B, pBl = base + 3 * PART_B;

#pragma unroll
        for (int ks = 0; ks < 4; ks++) {
            uint32_t ah[2][4], al[2][4], bh[2][4], bl[2][4];
#pragma unroll
            for (int mt = 0; mt < 2; mt++) {
                int arow = wm * 32 + mt * 16 + (lane & 15);
                uint32_t off = (uint32_t)arow * 128 + SWZC(ks * 32 + (lane >> 4) * 16, arow);
                LDSM4(ah[mt][0], ah[mt][1], ah[mt][2], ah[mt][3], pAh + off);
                LDSM4(al[mt][0], al[mt][1], al[mt][2], al[mt][3], pAl + off);
            }
#pragma unroll
            for (int np = 0; np < 2; np++) {
                int brow = wn * 32 + np * 16 + (lane & 7) + ((lane >> 4) << 3);
                uint32_t off = (uint32_t)brow * 128 +
                               SWZC(ks * 32 + ((lane >> 3) & 1) * 16, brow);
                LDSM4(bh[np][0], bh[np][1], bh[np][2], bh[np][3], pBh + off);
                LDSM4(bl[np][0], bl[np][1], bl[np][2], bl[np][3], pBl + off);
            }
#pragma unroll
            for (int np = 0; np < 2; np++)
#pragma unroll
                for (int mt = 0; mt < 2; mt++) {
                    mma_fp(acc0[mt][np * 2 + 0], ah[mt], bh[np] + 0);
                    mma_fp(acc0[mt][np * 2 + 1], ah[mt], bh[np] + 2);
                }
#pragma unroll
            for (int np = 0; np < 2; np++)
#pragma unroll
                for (int mt = 0; mt < 2; mt++) {
                    mma_fp(acc1[mt][np * 2 + 0], ah[mt], bl[np] + 0);
                    mma_fp(acc1[mt][np * 2 + 1], ah[mt], bl[np] + 2);
                }
#pragma unroll
            for (int np = 0; np < 2; np++)
#pragma unroll
                for (int mt = 0; mt < 2; mt++) {
                    mma_fp(acc1[mt][np * 2 + 0], al[mt], bh[np] + 0);
                    mma_fp(acc1[mt][np * 2 + 1], al[mt], bh[np] + 2);
                }
        }
        __syncthreads();
    }

#pragma unroll
    for (int mt = 0; mt < 2; mt++) {
#pragma unroll
        for (int hf = 0; hf < 2; hf++) {
            int gr = by * 128 + wm * 32 + mt * 16 + (lane >> 2) + hf * 8;
#pragma unroll
            for (int nt = 0; nt < 4; nt++) {
                int gn0 = bx * 128 + wn * 32 + nt * 8 + (lane & 3) * 2;
                float2 f2;
                f2.x = acc0[mt][nt][hf * 2 + 0] + acc1[mt][nt][hf * 2 + 0] * LO_INV;
                f2.y = acc0[mt][nt][hf * 2 + 1] + acc1[mt][nt][hf * 2 + 1] * LO_INV;
                *reinterpret_cast<float2*>(C + (long)gr * DIM + gn0) = f2;
            }
        }
    }
}

// ---------------------------------------------------------------------------
// S kernel: 1-pass fp16 mma; triangular + mirror; cooperative rescue. (512,2)
// BOTH output tiles staged in smem -> fully coalesced uint4 stores.
// ---------------------------------------------------------------------------
#define S1_STAGE (2 * PART_B)
#define S1_MAIN  (2 * S1_STAGE)                 // 64KB mainloop
#define S1_EPI   (2 * 128 * TSTRIDE * 2)        // 69.6KB epilogue staging
#define S1_DYN   (S1_EPI > S1_MAIN ? S1_EPI : S1_MAIN)
#define RMAX 512

__global__ __launch_bounds__(512, 2) void s_mma_kernel(
    const half* __restrict__ qn16, const float* __restrict__ qn,
    half* __restrict__ S)
{
    extern __shared__ __align__(1024) char sm[];
    __shared__ int rcount;
    __shared__ unsigned short rlist[RMAX];

    int tid = threadIdx.x;
    int wid = tid >> 5, lane = tid & 31;
    int wm = wid & 3, wn = wid >> 2;
    int bz = blockIdx.z;

    int t = blockIdx.x;
    int bi = (int)((sqrtf(8.0f * (float)t + 1.0f) - 1.0f) * 0.5f);
    while ((bi + 1) * (bi + 2) / 2 <= t) ++bi;
    while (bi * (bi + 1) / 2 > t) --bi;
    int by = t - bi * (bi + 1) / 2;
    int bx = bi;

    const half* At = qn16 + (long)bz * SEQ * DIM + (long)by * 128 * DIM;
    const half* Bt = qn16 + (long)bz * SEQ * DIM + (long)bx * 128 * DIM;

    uint32_t smb = smem_u32(sm);
    const int NC = DIM / KC;

    auto issue_chunk = [&](int c) {
        uint32_t st = smb + (uint32_t)(c & 1) * S1_STAGE;
        int k0 = c * KC;
        const half* srcs[2] = { At, Bt };
#pragma unroll
        for (int p = 0; p < 2; p++) {
#pragma unroll
            for (int i = 0; i < 2; i++) {
                int idx = tid + i * 512;
                int r = idx >> 3, c8 = idx & 7;
                uint32_t dst = st + (uint32_t)p * PART_B + (uint32_t)r * 128 + SWZC(c8 * 16, r);
                cp16(dst, srcs[p] + (long)r * DIM + k0 + c8 * 8);
            }
        }
        CP_COMMIT();
    };

    if (tid == 0) rcount = 0;

    float acc[2][4][4];
#pragma unroll
    for (int mt = 0; mt < 2; mt++)
#pragma unroll
        for (int nt = 0; nt < 4; nt++)
#pragma unroll
            for (int i = 0; i < 4; i++) acc[mt][nt][i] = 0.0f;

    issue_chunk(0);

    for (int c = 0; c < NC; c++) {
        if (c + 1 < NC) { issue_chunk(c + 1); CP_WAIT(1); }
        else            { CP_WAIT(0); }
        __syncthreads();

        uint32_t base = smb + (uint32_t)(c & 1) * S1_STAGE;
        uint32_t pA = base, pB = base + PART_B;

#pragma unroll
        for (int ks = 0; ks < 4; ks++) {
            uint32_t af[2][4], bfr[2][4];
#pragma unroll
            for (int mt = 0; mt < 2; mt++) {
                int arow = wm * 32 + mt * 16 + (lane & 15);
                uint32_t off = (uint32_t)arow * 128 + SWZC(ks * 32 + (lane >> 4) * 16, arow);
                LDSM4(af[mt][0], af[mt][1], af[mt][2], af[mt][3], pA + off);
            }
#pragma unroll
            for (int np = 0; np < 2; np++) {
                int brow = wn * 32 + np * 16 + (lane & 7) + ((lane >> 4) << 3);
                uint32_t off = (uint32_t)brow * 128 +
                               SWZC(ks * 32 + ((lane >> 3) & 1) * 16, brow);
                LDSM4(bfr[np][0], bfr[np][1], bfr[np][2], bfr[np][3], pB + off);
            }
#pragma unroll
            for (int np = 0; np < 2; np++)
#pragma unroll
                for (int mt = 0; mt < 2; mt++) {
                    mma_fp(acc[mt][np * 2 + 0], af[mt], bfr[np] + 0);
                    mma_fp(acc[mt][np * 2 + 1], af[mt], bfr[np] + 2);
                }
        }
        __syncthreads();
    }

    // ---- epilogue: stage thresholded tiles in smem + collect band entries
    const float* qnB = qn + (long)bz * SEQ * DIM;
    half* smD = reinterpret_cast<half*>(sm);            // direct [row][col]
    half* smT = smD + 128 * TSTRIDE;                    // mirror [col][row]
    half* Sb = S + (long)bz * SEQ * SEQ;
    bool mirror = (bx != by);

#pragma unroll
    for (int mt = 0; mt < 2; mt++) {
#pragma unroll
        for (int hf = 0; hf < 2; hf++) {
            int lr = wm * 32 + mt * 16 + (lane >> 2) + hf * 8;
            int gr = by * 128 + lr;
#pragma unroll
            for (int nt = 0; nt < 4; nt++) {
                float s0 = acc[mt][nt][hf * 2 + 0];
                float s1 = acc[mt][nt][hf * 2 + 1];
                int ln0 = wn * 32 + nt * 8 + (lane & 3) * 2;
                int gn0 = bx * 128 + ln0;
                if (fabsf(s0 - EPS_THR) < BAND) {
                    int p = atomicAdd(&rcount, 1);
                    if (p < RMAX) rlist[p] = (unsigned short)((lr << 8) | ln0);
                    else {
                        const float* qA = qnB + (long)gr * DIM;
                        const float* qB = qnB + (long)gn0 * DIM;
                        float a2 = 0.f;
#pragma unroll 8
                        for (int k = 0; k < DIM; k++) a2 = fmaf(qA[k], qB[k], a2);
                        s0 = a2;
                    }
                }
                if (fabsf(s1 - EPS_THR) < BAND) {
                    int p = atomicAdd(&rcount, 1);
                    if (p < RMAX) rlist[p] = (unsigned short)((lr << 8) | (ln0 + 1));
                    else {
                        const float* qA = qnB + (long)gr * DIM;
                        const float* qB = qnB + (long)(gn0 + 1) * DIM;
                        float a2 = 0.f;
#pragma unroll 8
                        for (int k = 0; k < DIM; k++) a2 = fmaf(qA[k], qB[k], a2);
                        s1 = a2;
                    }
                }
                s0 = (s0 > EPS_THR) ? s0 : 0.f;
                s1 = (s1 > EPS_THR) ? s1 : 0.f;
                half h0 = __float2half_rn(s0);
                half h1 = __float2half_rn(s1);
                smD[lr * TSTRIDE + ln0]     = h0;
                smD[lr * TSTRIDE + ln0 + 1] = h1;
                if (mirror) {
                    smT[ln0 * TSTRIDE + lr]       = h0;
                    smT[(ln0 + 1) * TSTRIDE + lr] = h1;
                }
            }
        }
    }
    __syncthreads();

    // ---- warp-cooperative rescue fix-up (in smem) ----
    {
        int nr = rcount < RMAX ? rcount : RMAX;
        for (int i = wid; i < nr; i += 16) {
            int code = rlist[i];
            int lr = code >> 8, ln = code & 255;
            int gr = by * 128 + lr, gn = bx * 128 + ln;
            const float* qA = qnB + (long)gr * DIM;
            const float* qB = qnB + (long)gn * DIM;
            float part = 0.f;
            int k0 = lane * 16;
#pragma unroll
            for (int k = 0; k < 16; k++) part = fmaf(qA[k0 + k], qB[k0 + k], part);
#pragma unroll
            for (int o = 16; o > 0; o >>= 1) part += __shfl_down_sync(0xffffffffu, part, o);
            if (lane == 0) {
                float sx = (part > EPS_THR) ? part : 0.f;
                half h = __float2half_rn(sx);
                smD[lr * TSTRIDE + ln] = h;
                if (mirror) smT[ln * TSTRIDE + lr] = h;
            }
        }
    }
    __syncthreads();

    // ---- coalesced writeout: direct tile (+ mirror tile) ----
    {
        int r2 = tid >> 2, q4 = tid & 3;
#pragma unroll
        for (int g = 0; g < 4; g++) {
            int j = q4 + g * 4;                  // 16 uint4 per 256B row
            uint4 v = *reinterpret_cast<const uint4*>(smD + r2 * TSTRIDE + j * 8);
            *reinterpret_cast<uint4*>(Sb + (long)(by * 128 + r2) * SEQ + bx * 128 + j * 8) = v;
        }
        if (mirror) {
#pragma unroll
            for (int g = 0; g < 4; g++) {
                int j = q4 + g * 4;
                uint4 v = *reinterpret_cast<const uint4*>(smT + r2 * TSTRIDE + j * 8);
                *reinterpret_cast<uint4*>(Sb + (long)(bx * 128 + r2) * SEQ + by * 128 + j * 8) = v;
            }
        }
    }
}

// ---------------------------------------------------------------------------
// fp16 1-pass mma GEMM, fp16 store: v = x * W_v^T. (512,2) — R13 form.
// ---------------------------------------------------------------------------
#define H_STAGE (2 * PART_B)
#define H_SMEM  (2 * H_STAGE)

__global__ __launch_bounds__(512, 2) void h_mma_kernel(
    const half* __restrict__ A, long ldA,
    const half* __restrict__ B, long ldB,
    int K, half* __restrict__ Oh, long ldO)
{
    extern __shared__ __align__(1024) char sm[];

    int tid = threadIdx.x;
    int wid = tid >> 5, lane = tid & 31;
    int wm = wid & 3, wn = wid >> 2;
    int bx = blockIdx.x, by = blockIdx.y;

    const half* At = A + (long)by * 128 * ldA;
    const half* Bt = B + (long)bx * 128 * ldB;

    uint32_t smb = smem_u32(sm);
    int NC = K / KC;

    auto issue_chunk = [&](int c) {
        uint32_t st = smb + (uint32_t)(c & 1) * H_STAGE;
        int k0 = c * KC;
        const half* srcs[2] = { At, Bt };
        long lds[2] = { ldA, ldB };
#pragma unroll
        for (int p = 0; p < 2; p++) {
#pragma unroll
            for (int i = 0; i < 2; i++) {
                int idx = tid + i * 512;
                int r = idx >> 3, c8 = idx & 7;
                uint32_t dst = st + (uint32_t)p * PART_B + (uint32_t)r * 128 + SWZC(c8 * 16, r);
                cp16(dst, srcs[p] + (long)r * lds[p] + k0 + c8 * 8);
            }
        }
        CP_COMMIT();
    };

    float acc[2][4][4];
#pragma unroll
    for (int mt = 0; mt < 2; mt++)
#pragma unroll
        for (int nt = 0; nt < 4; nt++)
#pragma unroll
            for (int i = 0; i < 4; i++) acc[mt][nt][i] = 0.0f;

    issue_chunk(0);

    for (int c = 0; c < NC; c++) {
        if (c + 1 < NC) { issue_chunk(c + 1); CP_WAIT(1); }
        else            { CP_WAIT(0); }
        __syncthreads();

        uint32_t base = smb + (uint32_t)(c & 1) * H_STAGE;
        uint32_t pA = base, pB = base + PART_B;

#pragma unroll
        for (int ks = 0; ks < 4; ks++) {
            uint32_t af[2][4], bfr[2][4];
#pragma unroll
            for (int mt = 0; mt < 2; mt++) {
                int arow = wm * 32 + mt * 16 + (lane & 15);
                uint32_t off = (uint32_t)arow * 128 + SWZC(ks * 32 + (lane >> 4) * 16, arow);
                LDSM4(af[mt][0], af[mt][1], af[mt][2], af[mt][3], pA + off);
            }
#pragma unroll
            for (int np = 0; np < 2; np++) {
                int brow = wn * 32 + np * 16 + (lane & 7) + ((lane >> 4) << 3);
                uint32_t off = (uint32_t)brow * 128 +
                               SWZC(ks * 32 + ((lane >> 3) & 1) * 16, brow);
                LDSM4(bfr[np][0], bfr[np][1], bfr[np][2], bfr[np][3], pB + off);
            }
#pragma unroll
            for (int np = 0; np < 2; np++)
#pragma unroll
                for (int mt = 0; mt < 2; mt++) {
                    mma_fp(acc[mt][np * 2 + 0], af[mt], bfr[np] + 0);
                    mma_fp(acc[mt][np * 2 + 1], af[mt], bfr[np] + 2);
                }
        }
        __syncthreads();
    }

#pragma unroll
    for (int mt = 0; mt < 2; mt++) {
#pragma unroll
        for (int hf = 0; hf < 2; hf++) {
            int gr = by * 128 + wm * 32 + mt * 16 + (lane >> 2) + hf * 8;
#pragma unroll
            for (int nt = 0; nt < 4; nt++) {
                int gn0 = bx * 128 + wn * 32 + nt * 8 + (lane & 3) * 2;
                half2 h = __floats2half2_rn(acc[mt][nt][hf * 2 + 0],
                                            acc[mt][nt][hf * 2 + 1]);
                *reinterpret_cast<half2*>(Oh + (long)gr * ldO + gn0) = h;
            }
        }
    }
}

// ---------------------------------------------------------------------------
// Sparse A*V + fused LayerNorm (R10/R13 4-phase version — frozen).
// ---------------------------------------------------------------------------
__global__ __launch_bounds__(128) void av_ln_kernel(
    const half* __restrict__ S, const half* __restrict__ V,
    const float* __restrict__ gamma, const float* __restrict__ beta,
    float* __restrict__ out)
{
    int gr = blockIdx.x;
    int bz = gr >> 12;
    int n  = gr & (SEQ - 1);
    const half* Srow = S + ((long)bz * SEQ + n) * SEQ;
    const half* Vb   = V + (long)bz * SEQ * DIM;
    int tid = threadIdx.x, lane = tid & 31, wrp = tid >> 5;

    __shared__ int   s_idx[1024];
    __shared__ float s_val[1024];
    __shared__ int   s_wbase[4];

    float a0 = 0.f, a1 = 0.f, a2 = 0.f, a3 = 0.f;

#pragma unroll 1
    for (int ch = 0; ch < SEQ / 1024; ch++) {
        uint4 w = *reinterpret_cast<const uint4*>(Srow + ch * 1024 + tid * 8);
        uint32_t ws[4] = { w.x, w.y, w.z, w.w };
        uint16_t hs[8];
#pragma unroll
        for (int k = 0; k < 4; k++) {
            hs[2 * k]     = (uint16_t)(ws[k] & 0xFFFFu);
            hs[2 * k + 1] = (uint16_t)(ws[k] >> 16);
        }
        int nz = 0;
#pragma unroll
        for (int k = 0; k < 8; k++) nz += (hs[k] != 0);

        int inc = nz;
#pragma unroll
        for (int o = 1; o < 32; o <<= 1) {
            int vsh = __shfl_up_sync(0xffffffffu, inc, o);
            if (lane >= o) inc += vsh;
        }
        if (lane == 31) s_wbase[wrp] = inc;
        __syncthreads();
        int wb = 0;
#pragma unroll
        for (int ww = 0; ww < 4; ww++) if (ww < wrp) wb += s_wbase[ww];
        int total = s_wbase[0] + s_wbase[1] + s_wbase[2] + s_wbase[3];
        int pos = wb + inc - nz;
#pragma unroll
        for (int k = 0; k < 8; k++) {
            if (hs[k] != 0) {
                __half_raw hr; hr.x = hs[k];
                s_idx[pos] = ch * 1024 + tid * 8 + k;
                s_val[pos] = __half2float((half)hr);
                pos++;
            }
        }
        __syncthreads();

        int i = 0;
        for (; i + 4 <= total; i += 4) {
            float sv0 = s_val[i],     sv1 = s_val[i + 1];
            float sv2 = s_val[i + 2], sv3 = s_val[i + 3];
            int m0 = s_idx[i],     m1 = s_idx[i + 1];
            int m2 = s_idx[i + 2], m3 = s_idx[i + 3];
            uint2 v0 = *reinterpret_cast<const uint2*>(Vb + (long)m0 * DIM + tid * 4);
            uint2 v1 = *reinterpret_cast<const uint2*>(Vb + (long)m1 * DIM + tid * 4);
            uint2 v2 = *reinterpret_cast<const uint2*>(Vb + (long)m2 * DIM + tid * 4);
            uint2 v3 = *reinterpret_cast<const uint2*>(Vb + (long)m3 * DIM + tid * 4);
#define ACC4(vv, sv) do {                                           \
                half2 _h0 = *reinterpret_cast<half2*>(&(vv).x);     \
                half2 _h1 = *reinterpret_cast<half2*>(&(vv).y);     \
                float2 _f0 = __half22float2(_h0);                   \
                float2 _f1 = __half22float2(_h1);                   \
                a0 = fmaf((sv), _f0.x, a0);                         \
                a1 = fmaf((sv), _f0.y, a1);                         \
                a2 = fmaf((sv), _f1.x, a2);                         \
                a3 = fmaf((sv), _f1.y, a3);                         \
            } while (0)
            ACC4(v0, sv0); ACC4(v1, sv1); ACC4(v2, sv2); ACC4(v3, sv3);
        }
        for (; i < total; i++) {
            float sv = s_val[i];
            int m = s_idx[i];
            uint2 vv = *reinterpret_cast<const uint2*>(Vb + (long)m * DIM + tid * 4);
            ACC4(vv, sv);
        }
#undef ACC4
        __syncthreads();
    }

    float s1 = a0 + a1 + a2 + a3;
    float s2 = a0 * a0 + a1 * a1 + a2 * a2 + a3 * a3;
    float ts1 = block_reduce_sum_128(s1);
    float ts2 = block_reduce_sum_128(s2);
    float mean = ts1 * (1.0f / DIM);
    float var  = ts2 * (1.0f / DIM) - mean * mean;
    float inv = rsqrtf(var + LN_EPS);

    float4 g = *reinterpret_cast<const float4*>(gamma + tid * 4);
    float4 b = *reinterpret_cast<const float4*>(beta + tid * 4);
    float4 o;
    o.x = (a0 - mean) * inv * g.x + b.x;
    o.y = (a1 - mean) * inv * g.y + b.y;
    o.z = (a2 - mean) * inv * g.z + b.z;
    o.w = (a3 - mean) * inv * g.w + b.w;
    *reinterpret_cast<float4*>(out + (long)gr * DIM + tid * 4) = o;
}

// ---------------------------------------------------------------------------
// Launch
// ---------------------------------------------------------------------------
extern "C" void kernel_launch(void* const* d_in, const int* in_sizes, int n_in,
                              void* d_out, int out_size)
{
    const float* x     = (const float*)d_in[0];
    const float* W_qk  = (const float*)d_in[1];
    const float* W_v   = (const float*)d_in[2];
    const float* gamma = (const float*)d_in[3];
    const float* beta  = (const float*)d_in[4];
    float* out = (float*)d_out;

    float* qp;
    half *qn16, *x16, *xlo, *w16, *whi, *wlo, *v16, *s16;
    cudaGetSymbolAddress((void**)&qp,   g_q);
    cudaGetSymbolAddress((void**)&qn16, g_qn16);
    cudaGetSymbolAddress((void**)&x16,  g_x16);
    cudaGetSymbolAddress((void**)&xlo,  g_xlo);
    cudaGetSymbolAddress((void**)&w16,  g_w16);
    cudaGetSymbolAddress((void**)&whi,  g_whi);
    cudaGetSymbolAddress((void**)&wlo,  g_wlo);
    cudaGetSymbolAddress((void**)&v16,  g_v16);
    cudaGetSymbolAddress((void**)&s16,  g_s16);

    cudaFuncSetAttribute((const void*)q_mma_kernel, cudaFuncAttributeMaxDynamicSharedMemorySize, Q_SMEM);
    cudaFuncSetAttribute((const void*)s_mma_kernel, cudaFuncAttributeMaxDynamicSharedMemorySize, S1_DYN);
    cudaFuncSetAttribute((const void*)h_mma_kernel, cudaFuncAttributeMaxDynamicSharedMemorySize, H_SMEM);

    // 1) merged splits
    split_all_kernel<<<((long)ROWS * DIM / 4 + 255) / 256, 256>>>(
        x, x16, xlo, W_qk, W_v, whi, wlo, w16);

    // 2) q = x * Wqk^T — 3-pass fp16 split, double-buffered (R13 form)
    {
        dim3 grid(DIM / 128, ROWS / 128, 1);
        q_mma_kernel<<<grid, 512, Q_SMEM>>>(x16, xlo, whi, wlo, qp);
    }

    // 3) v = x * W_v^T (fp16 1-pass; row-major)
    {
        dim3 grid(DIM / 128, ROWS / 128, 1);
        h_mma_kernel<<<grid, 512, H_SMEM>>>(x16, DIM, w16, DIM, DIM, v16, DIM);
    }

    // 4) L2-normalize q rows + fp16 plane
    l2norm_kernel<<<ROWS, 128>>>(qp, qn16);

    // 5) S = Qn*Qn^T — 1-pass fp16, triangular + mirror, rescue, coalesced stores
    {
        int nt = SEQ / 128;
        dim3 grid(nt * (nt + 1) / 2, 1, BATCH);
        s_mma_kernel<<<grid, 512, S1_DYN>>>(qn16, qp, s16);
    }

    // 6) out = LayerNorm(S * V) — sparse gather, fused LN
    av_ln_kernel<<<ROWS, 128>>>(s16, v16, gamma, beta, out);
}

// round 17
// speedup vs baseline: 1.5951x; 1.0070x over previous
#include <cuda_runtime.h>
#include <cuda_fp16.h>
#include <cstdint>
#include <math.h>

// ---------------------------------------------------------------------------
// Problem constants
// ---------------------------------------------------------------------------
#define BATCH 4
#define SEQ   4096
#define DIM   512
#define ROWS  (BATCH * SEQ)          // 16384
#define EPS_THR 0.1f
#define BAND    4e-4f
#define LN_EPS  1e-5f
#define NORM_EPS 1e-12f
#define LO_SCALE 2048.0f             // 2^11
#define LO_INV   (1.0f / 2048.0f)

// ---------------------------------------------------------------------------
// Scratch (__device__ globals; no runtime allocation)
// ---------------------------------------------------------------------------
__device__ float g_q   [(size_t)ROWS * DIM];          // fp32 q / qn
__device__ half  g_qn16[(size_t)ROWS * DIM];          // qn fp16
__device__ half  g_x16 [(size_t)ROWS * DIM];          // x fp16 hi
__device__ half  g_xlo [(size_t)ROWS * DIM];          // x fp16 lo * 2^11
__device__ half  g_w16 [(size_t)DIM * DIM];           // W_v fp16
__device__ half  g_whi [(size_t)DIM * DIM];           // W_qk fp16 hi
__device__ half  g_wlo [(size_t)DIM * DIM];           // W_qk fp16 lo * 2^11
__device__ half  g_v16 [(size_t)ROWS * DIM];          // v fp16 row-major
__device__ half  g_s16 [(size_t)BATCH * SEQ * SEQ];   // masked attn fp16

// ---------------------------------------------------------------------------
// PTX helpers (arch-agnostic: sm_80+)
// ---------------------------------------------------------------------------
__device__ __forceinline__ uint32_t smem_u32(const void* p) {
    uint32_t a;
    asm("{ .reg .u64 t; cvta.to.shared.u64 t, %1; cvt.u32.u64 %0, t; }"
        : "=r"(a) : "l"(p));
    return a;
}

__device__ __forceinline__ void cp16(uint32_t dst, const void* src) {
    asm volatile("cp.async.cg.shared.global [%0], [%1], 16;" :: "r"(dst), "l"(src));
}
#define CP_COMMIT() asm volatile("cp.async.commit_group;" ::: "memory")
#define CP_WAIT(n)  asm volatile("cp.async.wait_group %0;" :: "n"(n) : "memory")

#define LDSM4(r0, r1, r2, r3, addr) \
    asm volatile("ldmatrix.sync.aligned.m8n8.x4.shared.b16 {%0,%1,%2,%3},[%4];" \
                 : "=r"(r0), "=r"(r1), "=r"(r2), "=r"(r3) : "r"(addr))

__device__ __forceinline__ void mma_fp(float* c, const uint32_t* a, const uint32_t* b) {
    asm volatile(
        "mma.sync.aligned.m16n8k16.row.col.f32.f16.f16.f32 "
        "{%0,%1,%2,%3},{%4,%5,%6,%7},{%8,%9},{%0,%1,%2,%3};"
        : "+f"(c[0]), "+f"(c[1]), "+f"(c[2]), "+f"(c[3])
        : "r"(a[0]), "r"(a[1]), "r"(a[2]), "r"(a[3]), "r"(b[0]), "r"(b[1]));
}

#define SWZC(c, r) ((uint32_t)(c) ^ ((((uint32_t)(r)) & 7u) << 4))

#define KC      64
#define PART_B  16384                  // 128 rows x 128 bytes
#define TSTRIDE 136                    // halves; 272B (16B-aligned) row stride

// ---------------------------------------------------------------------------
// Merged split kernel: x -> (x16, xlo); W_qk -> (whi, wlo); W_v -> w16
// ---------------------------------------------------------------------------
__global__ __launch_bounds__(256) void split_all_kernel(
    const float* __restrict__ x, half* __restrict__ x16, half* __restrict__ xlo,
    const float* __restrict__ wqk, const float* __restrict__ wv,
    half* __restrict__ whi, half* __restrict__ wlo, half* __restrict__ w16)
{
    long i = ((long)blockIdx.x * 256 + threadIdx.x) * 4;
    if (i < (long)ROWS * DIM) {
        float4 f = *reinterpret_cast<const float4*>(x + i);
        float fv[4] = { f.x, f.y, f.z, f.w };
        half hi[4], lo[4];
#pragma unroll
        for (int k = 0; k < 4; k++) {
            hi[k] = __float2half_rn(fv[k]);
            lo[k] = __float2half_rn((fv[k] - __half2float(hi[k])) * LO_SCALE);
        }
        *reinterpret_cast<uint2*>(x16 + i) = *reinterpret_cast<uint2*>(hi);
        *reinterpret_cast<uint2*>(xlo + i) = *reinterpret_cast<uint2*>(lo);
    }
    if (i < (long)DIM * DIM) {
        float4 f = *reinterpret_cast<const float4*>(wqk + i);
        float fv[4] = { f.x, f.y, f.z, f.w };
        half hi[4], lo[4];
#pragma unroll
        for (int k = 0; k < 4; k++) {
            hi[k] = __float2half_rn(fv[k]);
            lo[k] = __float2half_rn((fv[k] - __half2float(hi[k])) * LO_SCALE);
        }
        *reinterpret_cast<uint2*>(whi + i) = *reinterpret_cast<uint2*>(hi);
        *reinterpret_cast<uint2*>(wlo + i) = *reinterpret_cast<uint2*>(lo);

        float4 g = *reinterpret_cast<const float4*>(wv + i);
        half2 h0 = __floats2half2_rn(g.x, g.y);
        half2 h1 = __floats2half2_rn(g.z, g.w);
        uint2 u;
        u.x = *reinterpret_cast<uint32_t*>(&h0);
        u.y = *reinterpret_cast<uint32_t*>(&h1);
        *reinterpret_cast<uint2*>(w16 + i) = u;
    }
}

// ---------------------------------------------------------------------------
// Block reduce (128 threads)
// ---------------------------------------------------------------------------
__device__ __forceinline__ float block_reduce_sum_128(float v)
{
    __shared__ float sh[4];
#pragma unroll
    for (int o = 16; o > 0; o >>= 1) v += __shfl_down_sync(0xffffffffu, v, o);
    int lane = threadIdx.x & 31, w = threadIdx.x >> 5;
    if (lane == 0) sh[w] = v;
    __syncthreads();
    float total = sh[0] + sh[1] + sh[2] + sh[3];
    __syncthreads();
    return total;
}

__global__ __launch_bounds__(128) void l2norm_kernel(
    float* __restrict__ q, half* __restrict__ q16)
{
    long base = (long)blockIdx.x * DIM;
    float* p = q + base;
    float s = 0.0f;
#pragma unroll
    for (int i = threadIdx.x; i < DIM; i += 128) { float v = p[i]; s += v * v; }
    float total = block_reduce_sum_128(s);
    float inv = 1.0f / fmaxf(sqrtf(total), NORM_EPS);
#pragma unroll
    for (int i = threadIdx.x; i < DIM; i += 128) {
        float v = p[i] * inv;
        p[i] = v;
        q16[base + i] = __float2half_rn(v);
    }
}

// ---------------------------------------------------------------------------
// Fused q + v projection: q = 3-pass fp16-split (bit-identical to R13/R16
// q_mma), v = 1-pass fp16 (bit-identical to old h_mma), sharing A-tiles.
// 5 planes/stage (xhi xlo whi wlo wv), double-buffered 160KB, 1 CTA/SM.
// ---------------------------------------------------------------------------
#define QV_STAGE (5 * PART_B)          // 80KB
#define QV_SMEM  (2 * QV_STAGE)        // 160KB

__global__ __launch_bounds__(512, 1) void qv_mma_kernel(
    const half* __restrict__ Ahi, const half* __restrict__ Alo,
    const half* __restrict__ Bhi, const half* __restrict__ Blo,
    const half* __restrict__ Bv,
    float* __restrict__ Cq, half* __restrict__ Cv)
{
    extern __shared__ __align__(1024) char sm[];

    int tid = threadIdx.x;
    int wid = tid >> 5, lane = tid & 31;
    int wm = wid & 3, wn = wid >> 2;
    int bx = blockIdx.x, by = blockIdx.y;

    const half* Ah = Ahi + (long)by * 128 * DIM;
    const half* Al = Alo + (long)by * 128 * DIM;
    const half* Bh = Bhi + (long)bx * 128 * DIM;
    const half* Bl = Blo + (long)bx * 128 * DIM;
    const half* Bw = Bv  + (long)bx * 128 * DIM;

    uint32_t smb = smem_u32(sm);
    const int NC = DIM / KC;

    auto issue_chunk = [&](int c) {
        uint32_t st = smb + (uint32_t)(c & 1) * QV_STAGE;
        int k0 = c * KC;
        const half* srcs[5] = { Ah, Al, Bh, Bl, Bw };
#pragma unroll
        for (int p = 0; p < 5; p++) {
#pragma unroll
            for (int i = 0; i < 2; i++) {
                int idx = tid + i * 512;
                int r = idx >> 3, c8 = idx & 7;
                uint32_t dst = st + (uint32_t)p * PART_B + (uint32_t)r * 128 + SWZC(c8 * 16, r);
                cp16(dst, srcs[p] + (long)r * DIM + k0 + c8 * 8);
            }
        }
        CP_COMMIT();
    };

    float acc0[2][4][4], acc1[2][4][4], accv[2][4][4];
#pragma unroll
    for (int mt = 0; mt < 2; mt++)
#pragma unroll
        for (int nt = 0; nt < 4; nt++)
#pragma unroll
            for (int i = 0; i < 4; i++) {
                acc0[mt][nt][i] = 0.0f; acc1[mt][nt][i] = 0.0f; accv[mt][nt][i] = 0.0f;
            }

    issue_chunk(0);

    for (int c = 0; c < NC; c++) {
        if (c + 1 < NC) { issue_chunk(c + 1); CP_WAIT(1); }
        else            { CP_WAIT(0); }
        __syncthreads();

        uint32_t base = smb + (uint32_t)(c & 1) * QV_STAGE;
        uint32_t pAh = base, pAl = base + PART_B, pBh = base + 2 * PART_B,
                 pBl = base + 3 * PART_B, pBv = base + 4 * PART_B;

#pragma unroll
        for (int ks = 0; ks < 4; ks++) {
            uint32_t ah[2][4], al[2][4], bh[2][4], bl[2][4], bv[2][4];
#pragma unroll
            for (int mt = 0; mt < 2; mt++) {
                int arow = wm * 32 + mt * 16 + (lane & 15);
                uint32_t off = (uint32_t)arow * 128 + SWZC(ks * 32 + (lane >> 4) * 16, arow);
                LDSM4(ah[mt][0], ah[mt][1], ah[mt][2], ah[mt][3], pAh + off);
                LDSM4(al[mt][0], al[mt][1], al[mt][2], al[mt][3], pAl + off);
            }
#pragma unroll
            for (int np = 0; np < 2; np++) {
                int brow = wn * 32 + np * 16 + (lane & 7) + ((lane >> 4) << 3);
                uint32_t off = (uint32_t)brow * 128 +
                               SWZC(ks * 32 + ((lane >> 3) & 1) * 16, brow);
                LDSM4(bh[np][0], bh[np][1], bh[np][2], bh[np][3], pBh + off);
                LDSM4(bl[np][0], bl[np][1], bl[np][2], bl[np][3], pBl + off);
                LDSM4(bv[np][0], bv[np][1], bv[np][2], bv[np][3], pBv + off);
            }
            // pass 1: hi*hi -> acc0   (identical order to R13/R16 q_mma)
#pragma unroll
            for (int np = 0; np < 2; np++)
#pragma unroll
                for (int mt = 0; mt < 2; mt++) {
                    mma_fp(acc0[mt][np * 2 + 0], ah[mt], bh[np] + 0);
                    mma_fp(acc0[mt][np * 2 + 1], ah[mt], bh[np] + 2);
                }
            // pass 2: hi*lo -> acc1
#pragma unroll
            for (int np = 0; np < 2; np++)
#pragma unroll
                for (int mt = 0; mt < 2; mt++) {
                    mma_fp(acc1[mt][np * 2 + 0], ah[mt], bl[np] + 0);
                    mma_fp(acc1[mt][np * 2 + 1], ah[mt], bl[np] + 2);
                }
            // pass 3: lo*hi -> acc1
#pragma unroll
            for (int np = 0; np < 2; np++)
#pragma unroll
                for (int mt = 0; mt < 2; mt++) {
                    mma_fp(acc1[mt][np * 2 + 0], al[mt], bh[np] + 0);
                    mma_fp(acc1[mt][np * 2 + 1], al[mt], bh[np] + 2);
                }
            // pass 4: v = xhi * wv -> accv   (identical order to old h_mma)
#pragma unroll
            for (int np = 0; np < 2; np++)
#pragma unroll
                for (int mt = 0; mt < 2; mt++) {
                    mma_fp(accv[mt][np * 2 + 0], ah[mt], bv[np] + 0);
                    mma_fp(accv[mt][np * 2 + 1], ah[mt], bv[np] + 2);
                }
        }
        __syncthreads();
    }

#pragma unroll
    for (int mt = 0; mt < 2; mt++) {
#pragma unroll
        for (int hf = 0; hf < 2; hf++) {
            int gr = by * 128 + wm * 32 + mt * 16 + (lane >> 2) + hf * 8;
#pragma unroll
            for (int nt = 0; nt < 4; nt++) {
                int gn0 = bx * 128 + wn * 32 + nt * 8 + (lane & 3) * 2;
                float2 f2;
                f2.x = acc0[mt][nt][hf * 2 + 0] + acc1[mt][nt][hf * 2 + 0] * LO_INV;
                f2.y = acc0[mt][nt][hf * 2 + 1] + acc1[mt][nt][hf * 2 + 1] * LO_INV;
                *reinterpret_cast<float2*>(Cq + (long)gr * DIM + gn0) = f2;
                half2 h = __floats2half2_rn(accv[mt][nt][hf * 2 + 0],
                                            accv[mt][nt][hf * 2 + 1]);
                *reinterpret_cast<half2*>(Cv + (long)gr * DIM + gn0) = h;
            }
        }
    }
}

// ---------------------------------------------------------------------------
// S kernel: 1-pass fp16 mma; triangular + mirror; cooperative rescue. (512,2)
// Both output tiles staged in smem -> coalesced uint4 stores. (R16 form)
// ---------------------------------------------------------------------------
#define S1_STAGE (2 * PART_B)
#define S1_MAIN  (2 * S1_STAGE)
#define S1_EPI   (2 * 128 * TSTRIDE * 2)
#define S1_DYN   (S1_EPI > S1_MAIN ? S1_EPI : S1_MAIN)
#define RMAX 512

__global__ __launch_bounds__(512, 2) void s_mma_kernel(
    const half* __restrict__ qn16, const float* __restrict__ qn,
    half* __restrict__ S)
{
    extern __shared__ __align__(1024) char sm[];
    __shared__ int rcount;
    __shared__ unsigned short rlist[RMAX];

    int tid = threadIdx.x;
    int wid = tid >> 5, lane = tid & 31;
    int wm = wid & 3, wn = wid >> 2;
    int bz = blockIdx.z;

    int t = blockIdx.x;
    int bi = (int)((sqrtf(8.0f * (float)t + 1.0f) - 1.0f) * 0.5f);
    while ((bi + 1) * (bi + 2) / 2 <= t) ++bi;
    while (bi * (bi + 1) / 2 > t) --bi;
    int by = t - bi * (bi + 1) / 2;
    int bx = bi;

    const half* At = qn16 + (long)bz * SEQ * DIM + (long)by * 128 * DIM;
    const half* Bt = qn16 + (long)bz * SEQ * DIM + (long)bx * 128 * DIM;

    uint32_t smb = smem_u32(sm);
    const int NC = DIM / KC;

    auto issue_chunk = [&](int c) {
        uint32_t st = smb + (uint32_t)(c & 1) * S1_STAGE;
        int k0 = c * KC;
        const half* srcs[2] = { At, Bt };
#pragma unroll
        for (int p = 0; p < 2; p++) {
#pragma unroll
            for (int i = 0; i < 2; i++) {
                int idx = tid + i * 512;
                int r = idx >> 3, c8 = idx & 7;
                uint32_t dst = st + (uint32_t)p * PART_B + (uint32_t)r * 128 + SWZC(c8 * 16, r);
                cp16(dst, srcs[p] + (long)r * DIM + k0 + c8 * 8);
            }
        }
        CP_COMMIT();
    };

    if (tid == 0) rcount = 0;

    float acc[2][4][4];
#pragma unroll
    for (int mt = 0; mt < 2; mt++)
#pragma unroll
        for (int nt = 0; nt < 4; nt++)
#pragma unroll
            for (int i = 0; i < 4; i++) acc[mt][nt][i] = 0.0f;

    issue_chunk(0);

    for (int c = 0; c < NC; c++) {
        if (c + 1 < NC) { issue_chunk(c + 1); CP_WAIT(1); }
        else            { CP_WAIT(0); }
        __syncthreads();

        uint32_t base = smb + (uint32_t)(c & 1) * S1_STAGE;
        uint32_t pA = base, pB = base + PART_B;

#pragma unroll
        for (int ks = 0; ks < 4; ks++) {
            uint32_t af[2][4], bfr[2][4];
#pragma unroll
            for (int mt = 0; mt < 2; mt++) {
                int arow = wm * 32 + mt * 16 + (lane & 15);
                uint32_t off = (uint32_t)arow * 128 + SWZC(ks * 32 + (lane >> 4) * 16, arow);
                LDSM4(af[mt][0], af[mt][1], af[mt][2], af[mt][3], pA + off);
            }
#pragma unroll
            for (int np = 0; np < 2; np++) {
                int brow = wn * 32 + np * 16 + (lane & 7) + ((lane >> 4) << 3);
                uint32_t off = (uint32_t)brow * 128 +
                               SWZC(ks * 32 + ((lane >> 3) & 1) * 16, brow);
                LDSM4(bfr[np][0], bfr[np][1], bfr[np][2], bfr[np][3], pB + off);
            }
#pragma unroll
            for (int np = 0; np < 2; np++)
#pragma unroll
                for (int mt = 0; mt < 2; mt++) {
                    mma_fp(acc[mt][np * 2 + 0], af[mt], bfr[np] + 0);
                    mma_fp(acc[mt][np * 2 + 1], af[mt], bfr[np] + 2);
                }
        }
        __syncthreads();
    }

    // ---- epilogue: stage thresholded tiles in smem + collect band entries
    const float* qnB = qn + (long)bz * SEQ * DIM;
    half* smD = reinterpret_cast<half*>(sm);
    half* smT = smD + 128 * TSTRIDE;
    half* Sb = S + (long)bz * SEQ * SEQ;
    bool mirror = (bx != by);

#pragma unroll
    for (int mt = 0; mt < 2; mt++) {
#pragma unroll
        for (int hf = 0; hf < 2; hf++) {
            int lr = wm * 32 + mt * 16 + (lane >> 2) + hf * 8;
            int gr = by * 128 + lr;
#pragma unroll
            for (int nt = 0; nt < 4; nt++) {
                float s0 = acc[mt][nt][hf * 2 + 0];
                float s1 = acc[mt][nt][hf * 2 + 1];
                int ln0 = wn * 32 + nt * 8 + (lane & 3) * 2;
                int gn0 = bx * 128 + ln0;
                if (fabsf(s0 - EPS_THR) < BAND) {
                    int p = atomicAdd(&rcount, 1);
                    if (p < RMAX) rlist[p] = (unsigned short)((lr << 8) | ln0);
                    else {
                        const float* qA = qnB + (long)gr * DIM;
                        const float* qB = qnB + (long)gn0 * DIM;
                        float a2 = 0.f;
#pragma unroll 8
                        for (int k = 0; k < DIM; k++) a2 = fmaf(qA[k], qB[k], a2);
                        s0 = a2;
                    }
                }
                if (fabsf(s1 - EPS_THR) < BAND) {
                    int p = atomicAdd(&rcount, 1);
                    if (p < RMAX) rlist[p] = (unsigned short)((lr << 8) | (ln0 + 1));
                    else {
                        const float* qA = qnB + (long)gr * DIM;
                        const float* qB = qnB + (long)(gn0 + 1) * DIM;
                        float a2 = 0.f;
#pragma unroll 8
                        for (int k = 0; k < DIM; k++) a2 = fmaf(qA[k], qB[k], a2);
                        s1 = a2;
                    }
                }
                s0 = (s0 > EPS_THR) ? s0 : 0.f;
                s1 = (s1 > EPS_THR) ? s1 : 0.f;
                half h0 = __float2half_rn(s0);
                half h1 = __float2half_rn(s1);
                smD[lr * TSTRIDE + ln0]     = h0;
                smD[lr * TSTRIDE + ln0 + 1] = h1;
                if (mirror) {
                    smT[ln0 * TSTRIDE + lr]       = h0;
                    smT[(ln0 + 1) * TSTRIDE + lr] = h1;
                }
            }
        }
    }
    __syncthreads();

    // ---- warp-cooperative rescue fix-up (in smem) ----
    {
        int nr = rcount < RMAX ? rcount : RMAX;
        for (int i = wid; i < nr; i += 16) {
            int code = rlist[i];
            int lr = code >> 8, ln = code & 255;
            int gr = by * 128 + lr, gn = bx * 128 + ln;
            const float* qA = qnB + (long)gr * DIM;
            const float* qB = qnB + (long)gn * DIM;
            float part = 0.f;
            int k0 = lane * 16;
#pragma unroll
            for (int k = 0; k < 16; k++) part = fmaf(qA[k0 + k], qB[k0 + k], part);
#pragma unroll
            for (int o = 16; o > 0; o >>= 1) part += __shfl_down_sync(0xffffffffu, part, o);
            if (lane == 0) {
                float sx = (part > EPS_THR) ? part : 0.f;
                half h = __float2half_rn(sx);
                smD[lr * TSTRIDE + ln] = h;
                if (mirror) smT[ln * TSTRIDE + lr] = h;
            }
        }
    }
    __syncthreads();

    // ---- coalesced writeout ----
    {
        int r2 = tid >> 2, q4 = tid & 3;
#pragma unroll
        for (int g = 0; g < 4; g++) {
            int j = q4 + g * 4;
            uint4 v = *reinterpret_cast<const uint4*>(smD + r2 * TSTRIDE + j * 8);
            *reinterpret_cast<uint4*>(Sb + (long)(by * 128 + r2) * SEQ + bx * 128 + j * 8) = v;
        }
        if (mirror) {
#pragma unroll
            for (int g = 0; g < 4; g++) {
                int j = q4 + g * 4;
                uint4 v = *reinterpret_cast<const uint4*>(smT + r2 * TSTRIDE + j * 8);
                *reinterpret_cast<uint4*>(Sb + (long)(bx * 128 + r2) * SEQ + by * 128 + j * 8) = v;
            }
        }
    }
}

// ---------------------------------------------------------------------------
// Sparse A*V + fused LayerNorm (R10/R13 4-phase version — frozen).
// ---------------------------------------------------------------------------
__global__ __launch_bounds__(128) void av_ln_kernel(
    const half* __restrict__ S, const half* __restrict__ V,
    const float* __restrict__ gamma, const float* __restrict__ beta,
    float* __restrict__ out)
{
    int gr = blockIdx.x;
    int bz = gr >> 12;
    int n  = gr & (SEQ - 1);
    const half* Srow = S + ((long)bz * SEQ + n) * SEQ;
    const half* Vb   = V + (long)bz * SEQ * DIM;
    int tid = threadIdx.x, lane = tid & 31, wrp = tid >> 5;

    __shared__ int   s_idx[1024];
    __shared__ float s_val[1024];
    __shared__ int   s_wbase[4];

    float a0 = 0.f, a1 = 0.f, a2 = 0.f, a3 = 0.f;

#pragma unroll 1
    for (int ch = 0; ch < SEQ / 1024; ch++) {
        uint4 w = *reinterpret_cast<const uint4*>(Srow + ch * 1024 + tid * 8);
        uint32_t ws[4] = { w.x, w.y, w.z, w.w };
        uint16_t hs[8];
#pragma unroll
        for (int k = 0; k < 4; k++) {
            hs[2 * k]     = (uint16_t)(ws[k] & 0xFFFFu);
            hs[2 * k + 1] = (uint16_t)(ws[k] >> 16);
        }
        int nz = 0;
#pragma unroll
        for (int k = 0; k < 8; k++) nz += (hs[k] != 0);

        int inc = nz;
#pragma unroll
        for (int o = 1; o < 32; o <<= 1) {
            int vsh = __shfl_up_sync(0xffffffffu, inc, o);
            if (lane >= o) inc += vsh;
        }
        if (lane == 31) s_wbase[wrp] = inc;
        __syncthreads();
        int wb = 0;
#pragma unroll
        for (int ww = 0; ww < 4; ww++) if (ww < wrp) wb += s_wbase[ww];
        int total = s_wbase[0] + s_wbase[1] + s_wbase[2] + s_wbase[3];
        int pos = wb + inc - nz;
#pragma unroll
        for (int k = 0; k < 8; k++) {
            if (hs[k] != 0) {
                __half_raw hr; hr.x = hs[k];
                s_idx[pos] = ch * 1024 + tid * 8 + k;
                s_val[pos] = __half2float((half)hr);
                pos++;
            }
        }
        __syncthreads();

        int i = 0;
        for (; i + 4 <= total; i += 4) {
            float sv0 = s_val[i],     sv1 = s_val[i + 1];
            float sv2 = s_val[i + 2], sv3 = s_val[i + 3];
            int m0 = s_idx[i],     m1 = s_idx[i + 1];
            int m2 = s_idx[i + 2], m3 = s_idx[i + 3];
            uint2 v0 = *reinterpret_cast<const uint2*>(Vb + (long)m0 * DIM + tid * 4);
            uint2 v1 = *reinterpret_cast<const uint2*>(Vb + (long)m1 * DIM + tid * 4);
            uint2 v2 = *reinterpret_cast<const uint2*>(Vb + (long)m2 * DIM + tid * 4);
            uint2 v3 = *reinterpret_cast<const uint2*>(Vb + (long)m3 * DIM + tid * 4);
#define ACC4(vv, sv) do {                                           \
                half2 _h0 = *reinterpret_cast<half2*>(&(vv).x);     \
                half2 _h1 = *reinterpret_cast<half2*>(&(vv).y);     \
                float2 _f0 = __half22float2(_h0);                   \
                float2 _f1 = __half22float2(_h1);                   \
                a0 = fmaf((sv), _f0.x, a0);                         \
                a1 = fmaf((sv), _f0.y, a1);                         \
                a2 = fmaf((sv), _f1.x, a2);                         \
                a3 = fmaf((sv), _f1.y, a3);                         \
            } while (0)
            ACC4(v0, sv0); ACC4(v1, sv1); ACC4(v2, sv2); ACC4(v3, sv3);
        }
        for (; i < total; i++) {
            float sv = s_val[i];
            int m = s_idx[i];
            uint2 vv = *reinterpret_cast<const uint2*>(Vb + (long)m * DIM + tid * 4);
            ACC4(vv, sv);
        }
#undef ACC4
        __syncthreads();
    }

    float s1 = a0 + a1 + a2 + a3;
    float s2 = a0 * a0 + a1 * a1 + a2 * a2 + a3 * a3;
    float ts1 = block_reduce_sum_128(s1);
    float ts2 = block_reduce_sum_128(s2);
    float mean = ts1 * (1.0f / DIM);
    float var  = ts2 * (1.0f / DIM) - mean * mean;
    float inv = rsqrtf(var + LN_EPS);

    float4 g = *reinterpret_cast<const float4*>(gamma + tid * 4);
    float4 b = *reinterpret_cast<const float4*>(beta + tid * 4);
    float4 o;
    o.x = (a0 - mean) * inv * g.x + b.x;
    o.y = (a1 - mean) * inv * g.y + b.y;
    o.z = (a2 - mean) * inv * g.z + b.z;
    o.w = (a3 - mean) * inv * g.w + b.w;
    *reinterpret_cast<float4*>(out + (long)gr * DIM + tid * 4) = o;
}

// ---------------------------------------------------------------------------
// Launch
// ---------------------------------------------------------------------------
extern "C" void kernel_launch(void* const* d_in, const int* in_sizes, int n_in,
                              void* d_out, int out_size)
{
    const float* x     = (const float*)d_in[0];
    const float* W_qk  = (const float*)d_in[1];
    const float* W_v   = (const float*)d_in[2];
    const float* gamma = (const float*)d_in[3];
    const float* beta  = (const float*)d_in[4];
    float* out = (float*)d_out;

    float* qp;
    half *qn16, *x16, *xlo, *w16, *whi, *wlo, *v16, *s16;
    cudaGetSymbolAddress((void**)&qp,   g_q);
    cudaGetSymbolAddress((void**)&qn16, g_qn16);
    cudaGetSymbolAddress((void**)&x16,  g_x16);
    cudaGetSymbolAddress((void**)&xlo,  g_xlo);
    cudaGetSymbolAddress((void**)&w16,  g_w16);
    cudaGetSymbolAddress((void**)&whi,  g_whi);
    cudaGetSymbolAddress((void**)&wlo,  g_wlo);
    cudaGetSymbolAddress((void**)&v16,  g_v16);
    cudaGetSymbolAddress((void**)&s16,  g_s16);

    cudaFuncSetAttribute((const void*)qv_mma_kernel, cudaFuncAttributeMaxDynamicSharedMemorySize, QV_SMEM);
    cudaFuncSetAttribute((const void*)s_mma_kernel,  cudaFuncAttributeMaxDynamicSharedMemorySize, S1_DYN);

    // 1) merged splits
    split_all_kernel<<<((long)ROWS * DIM / 4 + 255) / 256, 256>>>(
        x, x16, xlo, W_qk, W_v, whi, wlo, w16);

    // 2) fused q (3-pass fp16 split) + v (1-pass fp16) projection
    {
        dim3 grid(DIM / 128, ROWS / 128, 1);
        qv_mma_kernel<<<grid, 512, QV_SMEM>>>(x16, xlo, whi, wlo, w16, qp, v16);
    }

    // 3) L2-normalize q rows + fp16 plane
    l2norm_kernel<<<ROWS, 128>>>(qp, qn16);

    // 4) S = Qn*Qn^T — 1-pass fp16, triangular + mirror, rescue, coalesced stores
    {
        int nt = SEQ / 128;
        dim3 grid(nt * (nt + 1) / 2, 1, BATCH);
        s_mma_kernel<<<grid, 512, S1_DYN>>>(qn16, qp, s16);
    }

    // 5) out = LayerNorm(S * V) — sparse gather, fused LN
    av_ln_kernel<<<ROWS, 128>>>(s16, v16, gamma, beta, out);
}